// round 2
// baseline (speedup 1.0000x reference)
#include <cuda_runtime.h>
#include <cstdint>

// Problem shape (fixed by dataset): B=512, S=8192, C=4
#define SLEN 8192
#define NWORDS 256          // 32-bit mask words per row
#define NTHREADS 256

// XOR-swizzled CE index: conflict-free for both phase-A write and phase-B read
#define CEIDX(w, j) (((w) << 5) + ((j) ^ ((w) & 31)))

__device__ double g_sum;
__device__ unsigned long long g_cnt;

__global__ void init_kernel() {
    g_sum = 0.0;
    g_cnt = 0ull;
}

__global__ void fin_kernel(float* out) {
    unsigned long long c = g_cnt;
    if (c == 0ull) c = 1ull;
    out[0] = (float)(g_sum / (double)c);
}

// nearest set-bit distance around bit j of the middle word.
// lo = (mid << 32) | prev  (bit 32+j == position j, lower positions below)
// hi = (next << 32) | mid  (bit j == position j, higher positions above)
// Returns >= 6 (bucket ">TOL") whenever no bit within +-5; exact value for d<=5.
__device__ __forceinline__ int ndist(unsigned long long lo, unsigned long long hi, int j) {
    unsigned long long a = hi >> j;
    unsigned long long b = lo << (31 - j);
    int dr = a ? (__ffsll((long long)a) - 1) : 64;
    int dl = b ? __clzll((long long)b) : 64;
    return dr < dl ? dr : dl;
}

__global__ __launch_bounds__(NTHREADS)
void loss_kernel(const float* __restrict__ logits, const int* __restrict__ labels) {
    __shared__ float    s_ce[SLEN];       // 32 KB (swizzled)
    __shared__ unsigned s_valid[NWORDS];
    __shared__ unsigned s_podd[NWORDS];   // pred & 1 (mode)
    __shared__ unsigned s_p2[NWORDS];
    __shared__ unsigned s_p3[NWORDS];
    __shared__ unsigned s_lodd[NWORDS];   // (valid && (lab&1))
    __shared__ unsigned s_l2[NWORDS];
    __shared__ unsigned s_l3[NWORDS];
    __shared__ unsigned s_carry[NWORDS];  // packed exclusive carry: bit2=has, bit1=pm, bit0=tm
    __shared__ unsigned s_has[4];         // any-bit for p2, p3, l2, l3
    __shared__ double   s_red[8];
    __shared__ int      s_cnt[8];

    const int b    = blockIdx.x;
    const int tid  = threadIdx.x;
    const int lane = tid & 31;
    const int warp = tid >> 5;

    if (tid < 4) s_has[tid] = 0u;

    const float4* lg = reinterpret_cast<const float4*>(logits) + (size_t)b * SLEN;
    const int*    lb = labels + (size_t)b * SLEN;

    // ---------------- Phase A: stream row, compute CE, pack masks ----------------
    #pragma unroll 4
    for (int i = 0; i < SLEN / NTHREADS; ++i) {
        int s = i * NTHREADS + tid;
        float4 v = lg[s];
        int lab  = lb[s];
        bool valid = (lab != -100);

        // argmax with first-max tie semantics (strict >)
        int pred = 0; float best = v.x;
        if (v.y > best) { best = v.y; pred = 1; }
        if (v.z > best) { best = v.z; pred = 2; }
        if (v.w > best) { best = v.w; pred = 3; }

        // weighted CE = (logsumexp - logit[lab]) * W[lab], zeroed when invalid
        float m   = fmaxf(fmaxf(v.x, v.y), fmaxf(v.z, v.w));
        float e   = __expf(v.x - m) + __expf(v.y - m) + __expf(v.z - m) + __expf(v.w - m);
        float lse = m + __logf(e);
        float lv  = (lab == 1) ? v.y : (lab == 2) ? v.z : (lab == 3) ? v.w : v.x;
        float wc  = (lab == 2 || lab == 3) ? 30.0f : 1.0f;
        float ce  = valid ? (lse - lv) * wc : 0.0f;

        int word = i * 8 + warp;                 // warp lanes == word bits
        s_ce[CEIDX(word, lane)] = ce;

        unsigned bv  = __ballot_sync(0xffffffffu, valid);
        unsigned bpo = __ballot_sync(0xffffffffu, (pred & 1) != 0);
        unsigned bp2 = __ballot_sync(0xffffffffu, pred == 2);
        unsigned bp3 = __ballot_sync(0xffffffffu, pred == 3);
        unsigned blo = __ballot_sync(0xffffffffu, valid && ((lab & 1) != 0));
        unsigned bl2 = __ballot_sync(0xffffffffu, lab == 2);
        unsigned bl3 = __ballot_sync(0xffffffffu, lab == 3);
        if (lane == 0) {
            s_valid[word] = bv;  s_podd[word] = bpo;
            s_p2[word]    = bp2; s_p3[word]   = bp3;
            s_lodd[word]  = blo; s_l2[word]   = bl2; s_l3[word] = bl3;
        }
    }
    __syncthreads();

    // ---------------- has-flags + per-word summaries ----------------
    const int w = tid;
    unsigned mv = s_valid[w];
    atomicOr(&s_has[0], s_p2[w]);
    atomicOr(&s_has[1], s_p3[w]);
    atomicOr(&s_has[2], s_l2[w]);
    atomicOr(&s_has[3], s_l3[w]);

    unsigned summ = 0u;
    if (mv) {
        int jl = 31 - __clz(mv);               // last valid position in word
        summ = 4u | (((s_podd[w] >> jl) & 1u) << 1) | ((s_lodd[w] >> jl) & 1u);
    }
    s_carry[w] = summ;
    __syncthreads();

    // warp-0 scans 256 summaries (combine: b.has ? b : a), writes exclusive carries
    if (tid < 32) {
        unsigned sm8[8]; unsigned agg = 0u;
        #pragma unroll
        for (int k = 0; k < 8; ++k) {
            sm8[k] = s_carry[tid * 8 + k];
            if (sm8[k] & 4u) agg = sm8[k];
        }
        unsigned x = agg;
        #pragma unroll
        for (int off = 1; off < 32; off <<= 1) {
            unsigned y = __shfl_up_sync(0xffffffffu, x, off);
            if (tid >= off && !(x & 4u)) x = y;
        }
        unsigned ex = __shfl_up_sync(0xffffffffu, x, 1);
        if (tid == 0) ex = 0u;
        unsigned c = ex;
        #pragma unroll
        for (int k = 0; k < 8; ++k) {
            s_carry[tid * 8 + k] = c;
            if (sm8[k] & 4u) c = sm8[k];
        }
    }
    __syncthreads();

    // ---------------- Phase B: per-word state machine + proximity buckets ----------------
    unsigned carry = s_carry[w];
    int pm = (carry >> 1) & 1;
    int tm = carry & 1;

    unsigned mpo = s_podd[w], mp2 = s_p2[w], mp3 = s_p3[w];
    unsigned mlo = s_lodd[w], ml2 = s_l2[w], ml3 = s_l3[w];

    unsigned p2p = w ? s_p2[w - 1] : 0u, p2n = (w < NWORDS - 1) ? s_p2[w + 1] : 0u;
    unsigned p3p = w ? s_p3[w - 1] : 0u, p3n = (w < NWORDS - 1) ? s_p3[w + 1] : 0u;
    unsigned l2p = w ? s_l2[w - 1] : 0u, l2n = (w < NWORDS - 1) ? s_l2[w + 1] : 0u;
    unsigned l3p = w ? s_l3[w - 1] : 0u, l3n = (w < NWORDS - 1) ? s_l3[w + 1] : 0u;

    unsigned long long lo_p2 = ((unsigned long long)mp2 << 32) | p2p;
    unsigned long long hi_p2 = ((unsigned long long)p2n << 32) | mp2;
    unsigned long long lo_p3 = ((unsigned long long)mp3 << 32) | p3p;
    unsigned long long hi_p3 = ((unsigned long long)p3n << 32) | mp3;
    unsigned long long lo_l2 = ((unsigned long long)ml2 << 32) | l2p;
    unsigned long long hi_l2 = ((unsigned long long)l2n << 32) | ml2;
    unsigned long long lo_l3 = ((unsigned long long)ml3 << 32) | l3p;
    unsigned long long hi_l3 = ((unsigned long long)l3n << 32) | ml3;

    bool hP2 = s_has[0] != 0u, hP3 = s_has[1] != 0u;
    bool hT2 = s_has[2] != 0u, hT3 = s_has[3] != 0u;

    float acc = 0.0f;
    int cnt = __popc(mv);

    #pragma unroll 8
    for (int j = 0; j < 32; ++j) {
        if ((mv >> j) & 1u) {
            unsigned pr2 = (mp2 >> j) & 1u, pr3 = (mp3 >> j) & 1u;
            unsigned lb2 = (ml2 >> j) & 1u, lb3 = (ml3 >> j) & 1u;

            float mult = 1.0f;
            // invalid-transition penalty
            if ((pr2 && pm == 0) || (pr3 && pm == 1)) mult = 100.0f;
            // correct-switch bonus
            if ((lb2 && tm == 1 && pr2) || (lb3 && tm == 0 && pr3)) mult *= 0.1f;

            // class 2 proximity
            if (pr2) {
                if (hT2) {
                    int d = ndist(lo_l2, hi_l2, j);
                    float f = (d == 0) ? 0.1f
                            : (d == 1) ? 0.7f   : (d == 2) ? 0.49f
                            : (d == 3) ? 0.343f : (d == 4) ? 0.2401f
                            : (d == 5) ? 0.16807f : 10.0f;
                    mult *= f;
                } else mult *= 20.0f;
            }
            if (lb2) {
                if (hP2) { if (ndist(lo_p2, hi_p2, j) > 5) mult *= 2.0f; }
                else mult *= 3.0f;
            }
            // class 3 proximity
            if (pr3) {
                if (hT3) {
                    int d = ndist(lo_l3, hi_l3, j);
                    float f = (d == 0) ? 0.1f
                            : (d == 1) ? 0.7f   : (d == 2) ? 0.49f
                            : (d == 3) ? 0.343f : (d == 4) ? 0.2401f
                            : (d == 5) ? 0.16807f : 10.0f;
                    mult *= f;
                } else mult *= 20.0f;
            }
            if (lb3) {
                if (hP3) { if (ndist(lo_p3, hi_p3, j) > 5) mult *= 2.0f; }
                else mult *= 3.0f;
            }

            acc += s_ce[CEIDX(w, j)] * mult;

            // state-machine update (only at valid positions)
            pm = (mpo >> j) & 1u;
            tm = (mlo >> j) & 1u;
        }
    }

    // ---------------- block reduction -> global double atomics ----------------
    double a = (double)acc;
    #pragma unroll
    for (int off = 16; off > 0; off >>= 1) {
        a   += __shfl_down_sync(0xffffffffu, a, off);
        cnt += __shfl_down_sync(0xffffffffu, cnt, off);
    }
    if (lane == 0) { s_red[warp] = a; s_cnt[warp] = cnt; }
    __syncthreads();
    if (tid == 0) {
        double t = 0.0; int cc = 0;
        #pragma unroll
        for (int k = 0; k < 8; ++k) { t += s_red[k]; cc += s_cnt[k]; }
        atomicAdd(&g_sum, t);
        atomicAdd(&g_cnt, (unsigned long long)cc);
    }
}

extern "C" void kernel_launch(void* const* d_in, const int* in_sizes, int n_in,
                              void* d_out, int out_size) {
    const float* logits = (const float*)d_in[0];
    const int*   labels = (const int*)d_in[1];
    int B = in_sizes[1] / SLEN;

    init_kernel<<<1, 1>>>();
    loss_kernel<<<B, NTHREADS>>>(logits, labels);
    fin_kernel<<<1, 1>>>((float*)d_out);
}

// round 4
// speedup vs baseline: 1.4215x; 1.4215x over previous
#include <cuda_runtime.h>
#include <cstdint>

// Problem shape (fixed by dataset): B=512, S=8192, C=4
#define SLEN 8192
#define NWORDS 256          // 32-bit mask words per row
#define NTH 512
#define ITERS (SLEN / NTH)  // 16

// XOR-swizzled CE index: conflict-free for phase-A write and phase-B read
#define CEIDX(w, j) (((w) << 5) + ((j) ^ ((w) & 31)))

__device__ double g_part[1024];
__device__ int    g_pcnt[1024];
__device__ int    g_ticket;   // zero-initialized; last block resets it each run

// nearest set-bit distance around bit j of the middle word.
// lo = (mid << 32) | prev   (bit 32+j == position j, lower positions below)
// hi = (next << 32) | mid   (bit j == position j, higher positions above)
// Exact for d<=5; returns >=6 otherwise (only buckets matter, TOL=5).
__device__ __forceinline__ int ndist(unsigned long long lo, unsigned long long hi, int j) {
    unsigned long long a = hi >> j;
    unsigned long long b = lo << (31 - j);
    int dr = a ? (__ffsll((long long)a) - 1) : 64;
    int dl = b ? __clzll((long long)b) : 64;
    return dr < dl ? dr : dl;
}

// any set bit within distance 0..5 of position j (both directions)
__device__ __forceinline__ bool near5(unsigned long long lo, unsigned long long hi, int j) {
    unsigned up = (unsigned)(hi >> j) & 63u;          // distances 0..5 upward
    unsigned dn = (unsigned)(lo >> (j + 27)) & 63u;   // distances 0..5 downward
    return (up | dn) != 0u;
}

// DECAY^d table as a select tree (avoids divergent constant-bank replays)
__device__ __forceinline__ float decay_lut(int d) {
    float a  = (d == 0) ? 0.1f     : 0.7f;
    float bb = (d == 2) ? 0.49f    : 0.343f;
    float c  = (d == 4) ? 0.2401f  : 0.16807f;
    float lo = (d < 2) ? a : bb;
    float hi = (d < 6) ? c : 10.0f;
    return (d < 4) ? lo : hi;
}

__global__ __launch_bounds__(NTH)
void loss_kernel(const float* __restrict__ logits, const int* __restrict__ labels,
                 float* __restrict__ out, int B) {
    __shared__ float    s_ce[SLEN];       // 32 KB (swizzled)
    __shared__ unsigned s_valid[NWORDS];
    __shared__ unsigned s_podd[NWORDS];   // pred & 1 (mode)
    __shared__ unsigned s_p2[NWORDS];
    __shared__ unsigned s_p3[NWORDS];
    __shared__ unsigned s_lodd[NWORDS];   // valid && (lab & 1)
    __shared__ unsigned s_l2[NWORDS];
    __shared__ unsigned s_l3[NWORDS];
    __shared__ unsigned s_carry[NWORDS];  // packed exclusive carry: bit2=has, bit1=pm, bit0=tm
    __shared__ unsigned s_has[4];         // any-bit for p2, p3, l2, l3
    __shared__ double   s_red[16];
    __shared__ int      s_cnt[16];
    __shared__ int      s_last;

    const int b    = blockIdx.x;
    const int tid  = threadIdx.x;
    const int lane = tid & 31;
    const int warp = tid >> 5;

    if (tid < 4) s_has[tid] = 0u;

    const float4* lg = reinterpret_cast<const float4*>(logits) + (size_t)b * SLEN;
    const int*    lb = labels + (size_t)b * SLEN;

    // ---------------- Phase A: stream row, compute CE, pack masks ----------------
    #pragma unroll 4
    for (int i = 0; i < ITERS; ++i) {
        int s = i * NTH + tid;
        float4 v = lg[s];
        int lab  = lb[s];
        bool valid = (lab != -100);

        // argmax with first-max tie semantics (strict >); best ends as row max
        int pred = 0; float best = v.x;
        if (v.y > best) { best = v.y; pred = 1; }
        if (v.z > best) { best = v.z; pred = 2; }
        if (v.w > best) { best = v.w; pred = 3; }

        float m   = best;
        float e   = __expf(v.x - m) + __expf(v.y - m) + __expf(v.z - m) + __expf(v.w - m);
        float lse = m + __logf(e);
        float lv  = (lab == 1) ? v.y : (lab == 2) ? v.z : (lab == 3) ? v.w : v.x;
        float wc  = (lab == 2 || lab == 3) ? 30.0f : 1.0f;
        float ce  = valid ? (lse - lv) * wc : 0.0f;

        int word = i * (NTH / 32) + warp;        // warp lanes == word bits
        s_ce[CEIDX(word, lane)] = ce;

        unsigned bv  = __ballot_sync(0xffffffffu, valid);
        unsigned bpo = __ballot_sync(0xffffffffu, (pred & 1) != 0);
        unsigned bp2 = __ballot_sync(0xffffffffu, pred == 2);
        unsigned bp3 = __ballot_sync(0xffffffffu, pred == 3);
        unsigned blo = __ballot_sync(0xffffffffu, valid && ((lab & 1) != 0));
        unsigned bl2 = __ballot_sync(0xffffffffu, lab == 2);
        unsigned bl3 = __ballot_sync(0xffffffffu, lab == 3);
        if (lane == 0) {
            s_valid[word] = bv;  s_podd[word] = bpo;
            s_p2[word]    = bp2; s_p3[word]   = bp3;
            s_lodd[word]  = blo; s_l2[word]   = bl2; s_l3[word] = bl3;
        }
    }
    __syncthreads();

    // ---------------- has-flags + per-word summaries (threads 0..255) ----------------
    unsigned orv0 = 0, orv1 = 0, orv2 = 0, orv3 = 0;
    if (tid < NWORDS) {
        int ww = tid;
        orv0 = s_p2[ww]; orv1 = s_p3[ww]; orv2 = s_l2[ww]; orv3 = s_l3[ww];
        unsigned mvw = s_valid[ww];
        unsigned summ = 0u;
        if (mvw) {
            int jl = 31 - __clz(mvw);          // last valid position in word
            summ = 4u | (((s_podd[ww] >> jl) & 1u) << 1) | ((s_lodd[ww] >> jl) & 1u);
        }
        s_carry[ww] = summ;
    }
    {
        unsigned r0 = __reduce_or_sync(0xffffffffu, orv0);
        unsigned r1 = __reduce_or_sync(0xffffffffu, orv1);
        unsigned r2 = __reduce_or_sync(0xffffffffu, orv2);
        unsigned r3 = __reduce_or_sync(0xffffffffu, orv3);
        if (lane == 0) {
            if (r0) atomicOr(&s_has[0], 1u);
            if (r1) atomicOr(&s_has[1], 1u);
            if (r2) atomicOr(&s_has[2], 1u);
            if (r3) atomicOr(&s_has[3], 1u);
        }
    }
    __syncthreads();

    // warp-0 scans 256 summaries (combine: b.has ? b : a), writes exclusive carries
    if (tid < 32) {
        unsigned sm8[8]; unsigned agg = 0u;
        #pragma unroll
        for (int k = 0; k < 8; ++k) {
            sm8[k] = s_carry[tid * 8 + k];
            if (sm8[k] & 4u) agg = sm8[k];
        }
        unsigned x = agg;
        #pragma unroll
        for (int off = 1; off < 32; off <<= 1) {
            unsigned y = __shfl_up_sync(0xffffffffu, x, off);
            if (tid >= off && !(x & 4u)) x = y;
        }
        unsigned ex = __shfl_up_sync(0xffffffffu, x, 1);
        if (tid == 0) ex = 0u;
        unsigned c = ex;
        #pragma unroll
        for (int k = 0; k < 8; ++k) {
            s_carry[tid * 8 + k] = c;
            if (sm8[k] & 4u) c = sm8[k];
        }
    }
    __syncthreads();

    // ---------------- Phase B: 2 threads per word (16-bit halves) ----------------
    const int w = tid >> 1;
    const int h = tid & 1;

    unsigned mv  = s_valid[w];
    unsigned mpo = s_podd[w], mp2 = s_p2[w], mp3 = s_p3[w];
    unsigned mlo = s_lodd[w], ml2 = s_l2[w], ml3 = s_l3[w];

    unsigned carry = s_carry[w];
    int pm = (carry >> 1) & 1;
    int tm = carry & 1;
    if (h) {                                  // advance state through lower half
        unsigned low = mv & 0xFFFFu;
        if (low) {
            int jl = 31 - __clz(low);
            pm = (mpo >> jl) & 1;
            tm = (mlo >> jl) & 1;
        }
    }

    unsigned p2p = w ? s_p2[w - 1] : 0u, p2n = (w < NWORDS - 1) ? s_p2[w + 1] : 0u;
    unsigned p3p = w ? s_p3[w - 1] : 0u, p3n = (w < NWORDS - 1) ? s_p3[w + 1] : 0u;
    unsigned l2p = w ? s_l2[w - 1] : 0u, l2n = (w < NWORDS - 1) ? s_l2[w + 1] : 0u;
    unsigned l3p = w ? s_l3[w - 1] : 0u, l3n = (w < NWORDS - 1) ? s_l3[w + 1] : 0u;

    unsigned long long lo_p2 = ((unsigned long long)mp2 << 32) | p2p;
    unsigned long long hi_p2 = ((unsigned long long)p2n << 32) | mp2;
    unsigned long long lo_p3 = ((unsigned long long)mp3 << 32) | p3p;
    unsigned long long hi_p3 = ((unsigned long long)p3n << 32) | mp3;
    unsigned long long lo_l2 = ((unsigned long long)ml2 << 32) | l2p;
    unsigned long long hi_l2 = ((unsigned long long)l2n << 32) | ml2;
    unsigned long long lo_l3 = ((unsigned long long)ml3 << 32) | l3p;
    unsigned long long hi_l3 = ((unsigned long long)l3n << 32) | ml3;

    const bool hP2 = s_has[0] != 0u, hP3 = s_has[1] != 0u;
    const bool hT2 = s_has[2] != 0u, hT3 = s_has[3] != 0u;

    float acc = 0.0f;
    int   cnt = __popc(mv & (h ? 0xFFFF0000u : 0x0000FFFFu));
    const int j0 = h << 4;

    #pragma unroll
    for (int k = 0; k < 16; ++k) {
        int j = j0 + k;
        unsigned vb  = (mv  >> j) & 1u;
        unsigned pr2 = (mp2 >> j) & 1u, pr3 = (mp3 >> j) & 1u;
        unsigned lb2 = (ml2 >> j) & 1u, lb3 = (ml3 >> j) & 1u;

        unsigned bad  = (pr2 & (unsigned)(pm ^ 1)) | (pr3 & (unsigned)pm);
        unsigned good = (lb2 & (unsigned)tm & pr2) | (lb3 & (unsigned)(tm ^ 1) & pr3);

        float mult = bad ? 100.0f : 1.0f;
        mult = good ? mult * 0.1f : mult;

        // class-2 proximity (branchless / predicated)
        int   d2 = ndist(lo_l2, hi_l2, j);
        float f2 = hT2 ? decay_lut(d2) : 20.0f;
        mult = pr2 ? mult * f2 : mult;
        float g2 = hP2 ? (near5(lo_p2, hi_p2, j) ? 1.0f : 2.0f) : 3.0f;
        mult = lb2 ? mult * g2 : mult;

        // class-3 proximity
        int   d3 = ndist(lo_l3, hi_l3, j);
        float f3 = hT3 ? decay_lut(d3) : 20.0f;
        mult = pr3 ? mult * f3 : mult;
        float g3 = hP3 ? (near5(lo_p3, hi_p3, j) ? 1.0f : 2.0f) : 3.0f;
        mult = lb3 ? mult * g3 : mult;

        acc += vb ? s_ce[CEIDX(w, j)] * mult : 0.0f;

        pm = vb ? (int)((mpo >> j) & 1u) : pm;
        tm = vb ? (int)((mlo >> j) & 1u) : tm;
    }

    // ---------------- block reduction -> per-block partial ----------------
    double a = (double)acc;
    #pragma unroll
    for (int off = 16; off > 0; off >>= 1) {
        a   += __shfl_down_sync(0xffffffffu, a, off);
        cnt += __shfl_down_sync(0xffffffffu, cnt, off);
    }
    if (lane == 0) { s_red[warp] = a; s_cnt[warp] = cnt; }
    __syncthreads();
    if (tid == 0) {
        double t = 0.0; int cc = 0;
        #pragma unroll
        for (int k = 0; k < 16; ++k) { t += s_red[k]; cc += s_cnt[k]; }
        g_part[b] = t;
        g_pcnt[b] = cc;
        __threadfence();
        int ticket = atomicAdd(&g_ticket, 1);
        s_last = (ticket == (int)gridDim.x - 1) ? 1 : 0;
    }
    __syncthreads();

    // ---------------- last block finalizes (deterministic order) ----------------
    if (s_last) {
        double t = 0.0; int cc = 0;
        for (int i = tid; i < B; i += NTH) { t += g_part[i]; cc += g_pcnt[i]; }
        #pragma unroll
        for (int off = 16; off > 0; off >>= 1) {
            t  += __shfl_down_sync(0xffffffffu, t, off);
            cc += __shfl_down_sync(0xffffffffu, cc, off);
        }
        if (lane == 0) { s_red[warp] = t; s_cnt[warp] = cc; }
        __syncthreads();
        if (tid == 0) {
            double tt = 0.0; int c2 = 0;
            #pragma unroll
            for (int k = 0; k < 16; ++k) { tt += s_red[k]; c2 += s_cnt[k]; }
            if (c2 < 1) c2 = 1;
            out[0] = (float)(tt / (double)c2);
            g_ticket = 0;   // reset for next replay (determinism)
        }
    }
}

extern "C" void kernel_launch(void* const* d_in, const int* in_sizes, int n_in,
                              void* d_out, int out_size) {
    const float* logits = (const float*)d_in[0];
    const int*   labels = (const int*)d_in[1];
    int B = in_sizes[1] / SLEN;

    loss_kernel<<<B, NTH>>>(logits, labels, (float*)d_out, B);
}

// round 5
// speedup vs baseline: 1.9392x; 1.3642x over previous
#include <cuda_runtime.h>
#include <cstdint>

// Problem shape (fixed by dataset): B=512, S=8192, C=4
#define SLEN 8192
#define NWORDS 256          // 32-bit mask words per row
#define NTH 512
#define ITERS (SLEN / NTH)  // 16

// XOR-swizzled CE index: conflict-free for phase-A write and phase-B read
#define CEIDX(w, j) (((w) << 5) + ((j) ^ ((w) & 31)))

typedef unsigned long long ull;

__device__ double g_part[1024];
__device__ int    g_pcnt[1024];
__device__ int    g_ticket;   // zero-init; last block resets each run

__device__ __forceinline__ ull dil1(ull x) { return x | (x << 1) | (x >> 1); }

__global__ __launch_bounds__(NTH, 3)
void loss_kernel(const float* __restrict__ logits, const int* __restrict__ labels,
                 float* __restrict__ out, int B) {
    __shared__ float    s_ce[SLEN];       // 32 KB (swizzled)
    __shared__ unsigned s_valid[NWORDS];
    __shared__ unsigned s_podd[NWORDS];   // pred & 1 (mode)
    __shared__ unsigned s_p2[NWORDS];
    __shared__ unsigned s_p3[NWORDS];
    __shared__ unsigned s_lodd[NWORDS];   // valid && (lab & 1)
    __shared__ unsigned s_l2[NWORDS];
    __shared__ unsigned s_l3[NWORDS];
    __shared__ unsigned s_carry[NWORDS];  // exclusive carry: bit2=has, bit1=pm, bit0=tm
    __shared__ unsigned s_has[4];         // any-bit for p2, p3, l2, l3
    __shared__ double   s_red[16];
    __shared__ int      s_cnt[16];
    __shared__ int      s_last;

    const int b    = blockIdx.x;
    const int tid  = threadIdx.x;
    const int lane = tid & 31;
    const int warp = tid >> 5;

    if (tid < 4) s_has[tid] = 0u;

    const float4* lg = reinterpret_cast<const float4*>(logits) + (size_t)b * SLEN;
    const int*    lb = labels + (size_t)b * SLEN;

    // ---------------- Phase A: stream row, compute CE, pack masks ----------------
    #pragma unroll 4
    for (int i = 0; i < ITERS; ++i) {
        int s = i * NTH + tid;
        float4 v = lg[s];
        int lab  = lb[s];
        bool valid = (lab != -100);

        // argmax, first-max tie semantics (strict >); best ends as row max
        int pred = 0; float best = v.x;
        if (v.y > best) { best = v.y; pred = 1; }
        if (v.z > best) { best = v.z; pred = 2; }
        if (v.w > best) { best = v.w; pred = 3; }

        float m   = best;
        float e   = __expf(v.x - m) + __expf(v.y - m) + __expf(v.z - m) + __expf(v.w - m);
        float lse = m + __logf(e);
        float lv  = (lab == 1) ? v.y : (lab == 2) ? v.z : (lab == 3) ? v.w : v.x;
        float wc  = (lab == 2 || lab == 3) ? 30.0f : 1.0f;
        float ce  = valid ? (lse - lv) * wc : 0.0f;

        int word = i * (NTH / 32) + warp;        // warp lanes == word bits
        s_ce[CEIDX(word, lane)] = ce;

        unsigned bv  = __ballot_sync(0xffffffffu, valid);
        unsigned bpo = __ballot_sync(0xffffffffu, (pred & 1) != 0);
        unsigned bp2 = __ballot_sync(0xffffffffu, pred == 2);
        unsigned bp3 = __ballot_sync(0xffffffffu, pred == 3);
        unsigned blo = __ballot_sync(0xffffffffu, valid && ((lab & 1) != 0));
        unsigned bl2 = __ballot_sync(0xffffffffu, lab == 2);
        unsigned bl3 = __ballot_sync(0xffffffffu, lab == 3);
        if (lane == 0) {
            s_valid[word] = bv;  s_podd[word] = bpo;
            s_p2[word]    = bp2; s_p3[word]   = bp3;
            s_lodd[word]  = blo; s_l2[word]   = bl2; s_l3[word] = bl3;
        }
    }
    __syncthreads();

    // ---------------- has-flags + per-word summaries (threads 0..255) ----------------
    unsigned orv0 = 0, orv1 = 0, orv2 = 0, orv3 = 0;
    if (tid < NWORDS) {
        int ww = tid;
        orv0 = s_p2[ww]; orv1 = s_p3[ww]; orv2 = s_l2[ww]; orv3 = s_l3[ww];
        unsigned mvw = s_valid[ww];
        unsigned summ = 0u;
        if (mvw) {
            int jl = 31 - __clz(mvw);          // last valid position in word
            summ = 4u | (((s_podd[ww] >> jl) & 1u) << 1) | ((s_lodd[ww] >> jl) & 1u);
        }
        s_carry[ww] = summ;
    }
    {
        unsigned r0 = __reduce_or_sync(0xffffffffu, orv0);
        unsigned r1 = __reduce_or_sync(0xffffffffu, orv1);
        unsigned r2 = __reduce_or_sync(0xffffffffu, orv2);
        unsigned r3 = __reduce_or_sync(0xffffffffu, orv3);
        if (lane == 0) {
            if (r0) atomicOr(&s_has[0], 1u);
            if (r1) atomicOr(&s_has[1], 1u);
            if (r2) atomicOr(&s_has[2], 1u);
            if (r3) atomicOr(&s_has[3], 1u);
        }
    }
    __syncthreads();

    // warp-0 scans 256 summaries (combine: b.has ? b : a), writes exclusive carries
    if (tid < 32) {
        unsigned sm8[8]; unsigned agg = 0u;
        #pragma unroll
        for (int k = 0; k < 8; ++k) {
            sm8[k] = s_carry[tid * 8 + k];
            if (sm8[k] & 4u) agg = sm8[k];
        }
        unsigned x = agg;
        #pragma unroll
        for (int off = 1; off < 32; off <<= 1) {
            unsigned y = __shfl_up_sync(0xffffffffu, x, off);
            if (tid >= off && !(x & 4u)) x = y;
        }
        unsigned ex = __shfl_up_sync(0xffffffffu, x, 1);
        if (tid == 0) ex = 0u;
        unsigned c = ex;
        #pragma unroll
        for (int k = 0; k < 8; ++k) {
            s_carry[tid * 8 + k] = c;
            if (sm8[k] & 4u) c = sm8[k];
        }
    }
    __syncthreads();

    // ---------------- Phase B: bit-parallel, 2 threads per word ----------------
    const int w = tid >> 1;
    const int h = tid & 1;

    unsigned mv  = s_valid[w];
    unsigned mpo = s_podd[w];
    unsigned mlo = s_lodd[w];
    unsigned mp2 = s_p2[w], mp3 = s_p3[w];
    unsigned ml2 = s_l2[w], ml3 = s_l3[w];

    // Each pair-thread owns one class chain: h==0 -> class 2, h==1 -> class 3
    unsigned lt_m = h ? ml3 : ml2;
    unsigned pt_m = h ? mp3 : mp2;
    unsigned lt_p = 0, lt_n = 0, pt_p = 0, pt_n = 0;
    if (w > 0) {
        lt_p = h ? s_l3[w - 1] : s_l2[w - 1];
        pt_p = h ? s_p3[w - 1] : s_p2[w - 1];
    }
    if (w < NWORDS - 1) {
        lt_n = h ? s_l3[w + 1] : s_l2[w + 1];
        pt_n = h ? s_p3[w + 1] : s_p2[w + 1];
    }

    // exact-distance masks for the label-class chain (window: mid at bits 5..36)
    ull X  = ((ull)lt_n << 37) | ((ull)lt_m << 5) | (lt_p >> 27);
    ull D1 = dil1(X), D2 = dil1(D1), D3 = dil1(D2), D4 = dil1(D3), D5 = dil1(D4);
    unsigned e0 = (unsigned)(X >> 5);
    unsigned e1 = (unsigned)((D1 & ~X ) >> 5);
    unsigned e2 = (unsigned)((D2 & ~D1) >> 5);
    unsigned e3 = (unsigned)((D3 & ~D2) >> 5);
    unsigned e4 = (unsigned)((D4 & ~D3) >> 5);
    unsigned e5 = (unsigned)((D5 & ~D4) >> 5);

    // near-5 mask for the pred-class chain (only D5 needed; reach 1->2->4->5)
    ull Y  = ((ull)pt_n << 37) | ((ull)pt_m << 5) | (pt_p >> 27);
    ull Q1 = dil1(Y);
    ull Q2 = dil1(Q1);
    ull Q4 = Q2 | (Q2 << 2) | (Q2 >> 2);
    ull Q5 = dil1(Q4);
    unsigned n5own = (unsigned)(Q5 >> 5);

    // exchange with partner lane (lane ^ 1)
    unsigned f0 = __shfl_xor_sync(0xffffffffu, e0, 1);
    unsigned f1 = __shfl_xor_sync(0xffffffffu, e1, 1);
    unsigned f2 = __shfl_xor_sync(0xffffffffu, e2, 1);
    unsigned f3 = __shfl_xor_sync(0xffffffffu, e3, 1);
    unsigned f4 = __shfl_xor_sync(0xffffffffu, e4, 1);
    unsigned f5 = __shfl_xor_sync(0xffffffffu, e5, 1);
    unsigned n5oth = __shfl_xor_sync(0xffffffffu, n5own, 1);

    unsigned a0 = h ? f0 : e0, b0 = h ? e0 : f0;   // a* = class-2 exact-d, b* = class-3
    unsigned a1 = h ? f1 : e1, b1 = h ? e1 : f1;
    unsigned a2 = h ? f2 : e2, b2 = h ? e2 : f2;
    unsigned a3 = h ? f3 : e3, b3 = h ? e3 : f3;
    unsigned a4 = h ? f4 : e4, b4 = h ? e4 : f4;
    unsigned a5 = h ? f5 : e5, b5 = h ? e5 : f5;
    unsigned n5p2 = h ? n5oth : n5own;
    unsigned n5p3 = h ? n5own : n5oth;

    // combined bucket masks at pred positions
    unsigned m0 = (a0 & mp2) | (b0 & mp3);
    unsigned m1 = (a1 & mp2) | (b1 & mp3);
    unsigned m2 = (a2 & mp2) | (b2 & mp3);
    unsigned m3 = (a3 & mp2) | (b3 & mp3);
    unsigned m4 = (a4 & mp2) | (b4 & mp3);
    unsigned m5 = (a5 & mp2) | (b5 & mp3);
    unsigned prm = mp2 | mp3;

    // state streams via last-set-value fill (exclusive: bit j = state before j)
    unsigned carry = s_carry[w];
    unsigned Vp  = mv << 1;
    unsigned vpm = (mpo & mv) << 1;
    unsigned vtm = mlo << 1;                 // mlo already valid-masked
    unsigned has = Vp;
    #pragma unroll
    for (int k = 1; k < 32; k <<= 1) {
        unsigned nh = has << k;
        vpm = (has & vpm) | (~has & (vpm << k));
        vtm = (has & vtm) | (~has & (vtm << k));
        has |= nh;
    }
    unsigned PMm = vpm | (((carry >> 1) & 1u) ? ~has : 0u);
    unsigned TMm = vtm | ((carry & 1u) ? ~has : 0u);

    unsigned BAD  = (mp2 & ~PMm) | (mp3 & PMm);
    unsigned GOOD = (ml2 & TMm & mp2) | (ml3 & ~TMm & mp3);

    const bool hP2 = s_has[0] != 0u, hP3 = s_has[1] != 0u;
    const bool hT2 = s_has[2] != 0u, hT3 = s_has[3] != 0u;
    const float farF2 = hT2 ? 10.0f : 20.0f;
    const float farF3 = hT3 ? 10.0f : 20.0f;

    unsigned gm3 = (hP2 ? 0u : ml2) | (hP3 ? 0u : ml3);
    unsigned gm2 = (ml2 & (hP2 ? ~n5p2 : 0u)) | (ml3 & (hP3 ? ~n5p3 : 0u));

    float acc = 0.0f;
    int   cnt = __popc(mv & (h ? 0xFFFF0000u : 0x0000FFFFu));
    const int j0 = h << 4;

    #pragma unroll
    for (int k = 0; k < 16; ++k) {
        const int j = j0 + k;
        const unsigned bit = 1u << j;

        float F = (prm & bit) ? ((mp2 & bit) ? farF2 : farF3) : 1.0f;
        F = (m5 & bit) ? 0.16807f : F;
        F = (m4 & bit) ? 0.2401f  : F;
        F = (m3 & bit) ? 0.343f   : F;
        F = (m2 & bit) ? 0.49f    : F;
        F = (m1 & bit) ? 0.7f     : F;
        F = (m0 & bit) ? 0.1f     : F;

        float Bf = (BAD & bit) ? 100.0f : 1.0f;
        Bf = (GOOD & bit) ? Bf * 0.1f : Bf;

        float G = (gm3 & bit) ? 3.0f : ((gm2 & bit) ? 2.0f : 1.0f);

        // ce is 0 at invalid positions, so no validity gate needed
        acc += s_ce[CEIDX(w, j)] * (Bf * F * G);
    }

    // ---------------- block reduction -> per-block partial ----------------
    double a = (double)acc;
    #pragma unroll
    for (int off = 16; off > 0; off >>= 1) {
        a   += __shfl_down_sync(0xffffffffu, a, off);
        cnt += __shfl_down_sync(0xffffffffu, cnt, off);
    }
    if (lane == 0) { s_red[warp] = a; s_cnt[warp] = cnt; }
    __syncthreads();
    if (tid == 0) {
        double t = 0.0; int cc = 0;
        #pragma unroll
        for (int k = 0; k < 16; ++k) { t += s_red[k]; cc += s_cnt[k]; }
        g_part[b] = t;
        g_pcnt[b] = cc;
        __threadfence();
        int ticket = atomicAdd(&g_ticket, 1);
        s_last = (ticket == (int)gridDim.x - 1) ? 1 : 0;
    }
    __syncthreads();

    // ---------------- last block finalizes (deterministic order) ----------------
    if (s_last) {
        double t = 0.0; int cc = 0;
        for (int i = tid; i < B; i += NTH) { t += g_part[i]; cc += g_pcnt[i]; }
        #pragma unroll
        for (int off = 16; off > 0; off >>= 1) {
            t  += __shfl_down_sync(0xffffffffu, t, off);
            cc += __shfl_down_sync(0xffffffffu, cc, off);
        }
        if (lane == 0) { s_red[warp] = t; s_cnt[warp] = cc; }
        __syncthreads();
        if (tid == 0) {
            double tt = 0.0; int c2 = 0;
            #pragma unroll
            for (int k = 0; k < 16; ++k) { tt += s_red[k]; c2 += s_cnt[k]; }
            if (c2 < 1) c2 = 1;
            out[0] = (float)(tt / (double)c2);
            g_ticket = 0;   // reset for next replay (determinism)
        }
    }
}

extern "C" void kernel_launch(void* const* d_in, const int* in_sizes, int n_in,
                              void* d_out, int out_size) {
    const float* logits = (const float*)d_in[0];
    const int*   labels = (const int*)d_in[1];
    int B = in_sizes[1] / SLEN;

    loss_kernel<<<B, NTH>>>(logits, labels, (float*)d_out, B);
}